// round 6
// baseline (speedup 1.0000x reference)
#include <cuda_runtime.h>
#include <cuda_bf16.h>
#include <math.h>
#include <stdint.h>

// Problem constants
#define B_   8
#define T_   2048
#define DIM_ 512
#define NH_  8
#define NKV_ 4
#define HD_  64
#define EPS_ 1.1920928955078125e-07f
#define FREQ_C 0.41524101186091903f   // log2(10000)/32

typedef unsigned long long u64;
typedef uint32_t u32;

// ---------------- scratch (device globals; no allocation allowed) ----------
__device__ float g_qkv[(size_t)B_ * T_ * 1024];        // raw q|k|v projections
__device__ float g_y[(size_t)B_ * T_ * DIM_];          // attention output

// bf16 split operands for projections
__device__ __nv_bfloat16 g_xh[(size_t)B_ * T_ * DIM_];
__device__ __nv_bfloat16 g_xl[(size_t)B_ * T_ * DIM_];
__device__ __nv_bfloat16 g_yh[(size_t)B_ * T_ * DIM_];
__device__ __nv_bfloat16 g_yl[(size_t)B_ * T_ * DIM_];
__device__ __nv_bfloat16 g_wh[(size_t)1536 * DIM_];
__device__ __nv_bfloat16 g_wl[(size_t)1536 * DIM_];

// bf16 split attention operands
__device__ __nv_bfloat16 g_qh[(size_t)B_ * NH_ * T_ * HD_];   // [b][h][t][d], scaled 1/8
__device__ __nv_bfloat16 g_ql[(size_t)B_ * NH_ * T_ * HD_];
__device__ __nv_bfloat16 g_kh[(size_t)B_ * NKV_ * T_ * HD_];  // [b][kv][t][d]
__device__ __nv_bfloat16 g_kl[(size_t)B_ * NKV_ * T_ * HD_];
__device__ __nv_bfloat16 g_vth[(size_t)B_ * NKV_ * HD_ * T_]; // [b][kv][d][t]
__device__ __nv_bfloat16 g_vtl[(size_t)B_ * NKV_ * HD_ * T_];

// ---------------- small helpers -------------------------------------------
__device__ __forceinline__ u32 cvt2bf(float lo, float hi) {
    u32 r;
    asm("cvt.rn.bf16x2.f32 %0, %1, %2;" : "=r"(r) : "f"(hi), "f"(lo));
    return r;
}

__device__ __forceinline__ void mma_bf16(float* c, const u32* a, u32 b0, u32 b1) {
    asm volatile(
        "mma.sync.aligned.m16n8k16.row.col.f32.bf16.bf16.f32 "
        "{%0,%1,%2,%3}, {%4,%5,%6,%7}, {%8,%9}, {%0,%1,%2,%3};\n"
        : "+f"(c[0]), "+f"(c[1]), "+f"(c[2]), "+f"(c[3])
        : "r"(a[0]), "r"(a[1]), "r"(a[2]), "r"(a[3]), "r"(b0), "r"(b1));
}

__device__ __forceinline__ u32 s2u(const void* p) {
    return (u32)__cvta_generic_to_shared(p);
}

__device__ __forceinline__ void ldsm4(u32* r, u32 addr) {
    asm volatile(
        "ldmatrix.sync.aligned.m8n8.x4.shared.b16 {%0,%1,%2,%3}, [%4];"
        : "=r"(r[0]), "=r"(r[1]), "=r"(r[2]), "=r"(r[3]) : "r"(addr));
}

// ---------------- split fp32 -> bf16 hi/lo --------------------------------
__global__ __launch_bounds__(256) void split_kernel(
    const float* __restrict__ src, __nv_bfloat16* __restrict__ h,
    __nv_bfloat16* __restrict__ l)
{
    int i = blockIdx.x * 256 + threadIdx.x;
    float x = src[i];
    __nv_bfloat16 hh = __float2bfloat16(x);
    float r = x - __bfloat162float(hh);
    h[i] = hh;
    l[i] = __float2bfloat16(r);
}

// ---------------- bf16-split tensor-core GEMM (ldmatrix) ------------------
#define LDSB 40

__global__ __launch_bounds__(256) void gemm_bf16_kernel(
    const __nv_bfloat16* __restrict__ Ah, const __nv_bfloat16* __restrict__ Al,
    int wrow0, float* __restrict__ C, int ldc, int coff)
{
    __shared__ __nv_bfloat16 sAh[128 * LDSB];
    __shared__ __nv_bfloat16 sAl[128 * LDSB];
    __shared__ __nv_bfloat16 sWh[128 * LDSB];
    __shared__ __nv_bfloat16 sWl[128 * LDSB];

    const int tid  = threadIdx.x;
    const int m0   = blockIdx.x * 128;
    const int n0   = blockIdx.y * 128;
    const int lane = tid & 31;
    const int wid  = tid >> 5;
    const int wm   = (wid >> 2) * 64;
    const int wn   = (wid & 3) * 32;
    const int g    = lane >> 2;
    const int t2   = (lane & 3) * 2;

    // ldmatrix lane-address components
    const int arow = lane & 15;            // A: row within 16
    const int ac8  = (lane >> 4) * 8;      // A: k-subcolumn
    const int brow = ((lane >> 4) * 8) + (lane & 7);  // B: row within 16 (nt pair)
    const int bc8  = ((lane >> 3) & 1) * 8;           // B: k-subcolumn

    const u32 aAh = s2u(sAh), aAl = s2u(sAl);
    const u32 aWh = s2u(sWh), aWl = s2u(sWl);

    const __nv_bfloat16* Wh = g_wh + (size_t)wrow0 * 512;
    const __nv_bfloat16* Wl = g_wl + (size_t)wrow0 * 512;

    float acc[4][4][4];
#pragma unroll
    for (int i = 0; i < 4; i++)
#pragma unroll
        for (int j = 0; j < 4; j++)
#pragma unroll
            for (int q = 0; q < 4; q++) acc[i][j][q] = 0.f;

    const int l_row0 = tid >> 2;
    const int l_c4   = tid & 3;

    uint4 pAh[2], pAl[2], pWh[2], pWl[2];
#pragma unroll
    for (int p = 0; p < 2; p++) {
        int row = l_row0 + p * 64;
        size_t ao = (size_t)(m0 + row) * 512 + l_c4 * 8;
        size_t wo = (size_t)(n0 + row) * 512 + l_c4 * 8;
        pAh[p] = *(const uint4*)(Ah + ao);
        pAl[p] = *(const uint4*)(Al + ao);
        pWh[p] = *(const uint4*)(Wh + wo);
        pWl[p] = *(const uint4*)(Wl + wo);
    }

    for (int it = 0; it < 16; it++) {
#pragma unroll
        for (int p = 0; p < 2; p++) {
            int row = l_row0 + p * 64;
            int so = row * LDSB + l_c4 * 8;
            *(uint4*)(sAh + so) = pAh[p];
            *(uint4*)(sAl + so) = pAl[p];
            *(uint4*)(sWh + so) = pWh[p];
            *(uint4*)(sWl + so) = pWl[p];
        }
        __syncthreads();

        if (it < 15) {
            int k0 = (it + 1) * 32;
#pragma unroll
            for (int p = 0; p < 2; p++) {
                int row = l_row0 + p * 64;
                size_t ao = (size_t)(m0 + row) * 512 + k0 + l_c4 * 8;
                size_t wo = (size_t)(n0 + row) * 512 + k0 + l_c4 * 8;
                pAh[p] = *(const uint4*)(Ah + ao);
                pAl[p] = *(const uint4*)(Al + ao);
                pWh[p] = *(const uint4*)(Wh + wo);
                pWl[p] = *(const uint4*)(Wl + wo);
            }
        }

#pragma unroll
        for (int ks = 0; ks < 32; ks += 16) {
            u32 ah[4][4], al[4][4];
#pragma unroll
            for (int mt = 0; mt < 4; mt++) {
                u32 off = (u32)(((wm + mt * 16 + arow) * LDSB + ks + ac8) * 2);
                ldsm4(ah[mt], aAh + off);
                ldsm4(al[mt], aAl + off);
            }
            u32 bh[8], bl[8];   // [nt*2 + (b0/b1)]
#pragma unroll
            for (int p = 0; p < 2; p++) {
                u32 off = (u32)(((wn + p * 16 + brow) * LDSB + ks + bc8) * 2);
                ldsm4(bh + p * 4, aWh + off);
                ldsm4(bl + p * 4, aWl + off);
            }
#pragma unroll
            for (int nt = 0; nt < 4; nt++) {
                u32 bh0 = bh[nt * 2], bh1 = bh[nt * 2 + 1];
                u32 bl0 = bl[nt * 2], bl1 = bl[nt * 2 + 1];
#pragma unroll
                for (int mt = 0; mt < 4; mt++) {
                    mma_bf16(acc[mt][nt], ah[mt], bh0, bh1);
                    mma_bf16(acc[mt][nt], ah[mt], bl0, bl1);
                    mma_bf16(acc[mt][nt], al[mt], bh0, bh1);
                }
            }
        }
        __syncthreads();
    }

#pragma unroll
    for (int mt = 0; mt < 4; mt++) {
#pragma unroll
        for (int nt = 0; nt < 4; nt++) {
            int row = m0 + wm + mt * 16 + g;
            int col = coff + n0 + wn + nt * 8 + t2;
            float* c = acc[mt][nt];
            *(float2*)&C[(size_t)row * ldc + col] = make_float2(c[0], c[1]);
            *(float2*)&C[(size_t)(row + 8) * ldc + col] = make_float2(c[2], c[3]);
        }
    }
}

// ---------------- RMSNorm + RoPE -> split bf16 Q/K ------------------------
__device__ __forceinline__ void norm_rope_split(
    const float* __restrict__ src, __nv_bfloat16* __restrict__ dh,
    __nv_bfloat16* __restrict__ dl, int lane, float cv, float sv, float scale)
{
    float x1 = src[lane];
    float x2 = src[lane + 32];
    float ss = x1 * x1 + x2 * x2;
#pragma unroll
    for (int off = 16; off > 0; off >>= 1)
        ss += __shfl_xor_sync(0xffffffffu, ss, off);
    float ir = rsqrtf(ss * (1.f / 64.f) + EPS_) * scale;
    x1 *= ir;
    x2 *= ir;
    float o1 = x1 * cv + x2 * sv;
    float o2 = x2 * cv - x1 * sv;
    __nv_bfloat16 h1 = __float2bfloat16(o1);
    __nv_bfloat16 h2 = __float2bfloat16(o2);
    dh[lane]      = h1;
    dh[lane + 32] = h2;
    dl[lane]      = __float2bfloat16(o1 - __bfloat162float(h1));
    dl[lane + 32] = __float2bfloat16(o2 - __bfloat162float(h2));
}

__global__ __launch_bounds__(256) void rope_kernel()
{
    const int tok = blockIdx.x;
    const int b = tok >> 11;
    const int t = tok & (T_ - 1);
    const int lane = threadIdx.x & 31;
    const int w = threadIdx.x >> 5;

    const float* row = g_qkv + (size_t)tok * 1024;

    float inv_freq = exp2f(-(float)lane * FREQ_C);
    float f = (float)t * inv_freq;
    float sv, cv;
    sincosf(f, &sv, &cv);

    size_t qo = (((size_t)b * NH_ + w) * T_ + t) * HD_;
    norm_rope_split(row + w * 64, g_qh + qo, g_ql + qo, lane, cv, sv, 0.125f);
    if (w < 4) {
        size_t ko = (((size_t)b * NKV_ + w) * T_ + t) * HD_;
        norm_rope_split(row + 512 + w * 64, g_kh + ko, g_kl + ko,
                        lane, cv, sv, 1.0f);
    }
}

// ---------------- V transpose + split: g_qkv -> [b][kv][d][t] bf16 --------
__global__ __launch_bounds__(256) void vtrans_kernel()
{
    __shared__ float vs[64][65];
    const int tid = threadIdx.x;
    const int t0 = blockIdx.x * 64;
    const int kv = blockIdx.y;
    const int b  = blockIdx.z;

#pragma unroll
    for (int p = 0; p < 4; p++) {
        int tl = (tid >> 4) + p * 16;
        int d4 = (tid & 15) * 4;
        float4 v = *(const float4*)&g_qkv[((size_t)(b * T_ + t0 + tl) * 1024)
                                          + 768 + kv * 64 + d4];
        vs[tl][d4 + 0] = v.x;
        vs[tl][d4 + 1] = v.y;
        vs[tl][d4 + 2] = v.z;
        vs[tl][d4 + 3] = v.w;
    }
    __syncthreads();

    const int d = tid >> 2;
    const int ts = (tid & 3) * 16;
    size_t base = (((size_t)(b * NKV_ + kv) * HD_) + d) * T_ + t0 + ts;
#pragma unroll
    for (int i = 0; i < 16; i++) {
        float x = vs[ts + i][d];
        __nv_bfloat16 h = __float2bfloat16(x);
        g_vth[base + i] = h;
        g_vtl[base + i] = __float2bfloat16(x - __bfloat162float(h));
    }
}

// ---------------- tensor-core causal flash attention ----------------------
// 128 threads (4 warps). Q tile 64 rows (16/warp), KV tile 32.
// Q fragments register-resident; all smem frag loads via ldmatrix.
#define KSTR 72
#define VSTR 40

__global__ __launch_bounds__(128) void attn_kernel()
{
    __shared__ __nv_bfloat16 sQh[64 * KSTR], sQl[64 * KSTR];
    __shared__ __nv_bfloat16 sKh[32 * KSTR], sKl[32 * KSTR];
    __shared__ __nv_bfloat16 sVh[64 * VSTR], sVl[64 * VSTR];

    const int tid  = threadIdx.x;
    const int lane = tid & 31;
    const int wid  = tid >> 5;
    const int wq   = wid * 16;
    const int g    = lane >> 2;
    const int t2   = (lane & 3) * 2;

    const int arow = lane & 15;
    const int ac8  = (lane >> 4) * 8;
    const int brow = ((lane >> 4) * 8) + (lane & 7);
    const int bc8  = ((lane >> 3) & 1) * 8;

    const int q0 = (gridDim.x - 1 - blockIdx.x) * 64;  // heavy tiles first
    const int h  = blockIdx.y;
    const int b  = blockIdx.z;
    const int kvh = h >> 1;

    // load Q tile into smem
    {
        const __nv_bfloat16* qbh = g_qh + (((size_t)b * NH_ + h) * T_ + q0) * HD_;
        const __nv_bfloat16* qbl = g_ql + (((size_t)b * NH_ + h) * T_ + q0) * HD_;
#pragma unroll
        for (int p = 0; p < 4; p++) {
            int i = tid + p * 128;
            int row = i >> 3, c = i & 7;
            *(uint4*)(sQh + row * KSTR + c * 8) = ((const uint4*)qbh)[i];
            *(uint4*)(sQl + row * KSTR + c * 8) = ((const uint4*)qbl)[i];
        }
    }
    __syncthreads();

    // hoist Q fragments into registers (all 4 k-chunks, hi+lo)
    u32 qfh[4][4], qfl[4][4];
    {
        const u32 aQh = s2u(sQh), aQl = s2u(sQl);
#pragma unroll
        for (int ktile = 0; ktile < 4; ktile++) {
            u32 off = (u32)(((wq + arow) * KSTR + ktile * 16 + ac8) * 2);
            ldsm4(qfh[ktile], aQh + off);
            ldsm4(qfl[ktile], aQl + off);
        }
    }

    const int row0 = q0 + wq + g;
    const int row1 = row0 + 8;

    float m0 = -1e30f, m1 = -1e30f, l0 = 0.f, l1 = 0.f;
    float O[8][4];
#pragma unroll
    for (int n = 0; n < 8; n++)
#pragma unroll
        for (int q = 0; q < 4; q++) O[n][q] = 0.f;

    const __nv_bfloat16* kbh = g_kh + (((size_t)b * NKV_ + kvh) * T_) * HD_;
    const __nv_bfloat16* kbl = g_kl + (((size_t)b * NKV_ + kvh) * T_) * HD_;
    const __nv_bfloat16* vbh = g_vth + (((size_t)b * NKV_ + kvh) * HD_) * T_;
    const __nv_bfloat16* vbl = g_vtl + (((size_t)b * NKV_ + kvh) * HD_) * T_;

    const u32 aKh = s2u(sKh), aKl = s2u(sKl);
    const u32 aVh = s2u(sVh), aVl = s2u(sVl);

    const int nkt = q0 / 32 + 2;

    for (int kt = 0; kt < nkt; kt++) {
        const int kv0 = kt * 32;
#pragma unroll
        for (int p = 0; p < 2; p++) {
            int i = tid + p * 128;
            int kr = i >> 3, kc = i & 7;
            *(uint4*)(sKh + kr * KSTR + kc * 8) =
                *(const uint4*)(kbh + (size_t)(kv0 + kr) * HD_ + kc * 8);
            *(uint4*)(sKl + kr * KSTR + kc * 8) =
                *(const uint4*)(kbl + (size_t)(kv0 + kr) * HD_ + kc * 8);
            int vr = i >> 2, vc = i & 3;
            *(uint4*)(sVh + vr * VSTR + vc * 8) =
                *(const uint4*)(vbh + (size_t)vr * T_ + kv0 + vc * 8);
            *(uint4*)(sVl + vr * VSTR + vc * 8) =
                *(const uint4*)(vbl + (size_t)vr * T_ + kv0 + vc * 8);
        }
        __syncthreads();

        // S = Q K^T (3-term split)
        float S[4][4];
#pragma unroll
        for (int n = 0; n < 4; n++)
#pragma unroll
            for (int q = 0; q < 4; q++) S[n][q] = 0.f;

#pragma unroll
        for (int ktile = 0; ktile < 4; ktile++) {
            u32 kh[8], kl[8];   // [nt*2 + b-reg]
#pragma unroll
            for (int p = 0; p < 2; p++) {
                u32 off = (u32)(((p * 16 + brow) * KSTR + ktile * 16 + bc8) * 2);
                ldsm4(kh + p * 4, aKh + off);
                ldsm4(kl + p * 4, aKl + off);
            }
#pragma unroll
            for (int nt = 0; nt < 4; nt++) {
                mma_bf16(S[nt], qfh[ktile], kh[nt * 2], kh[nt * 2 + 1]);
                mma_bf16(S[nt], qfh[ktile], kl[nt * 2], kl[nt * 2 + 1]);
                mma_bf16(S[nt], qfl[ktile], kh[nt * 2], kh[nt * 2 + 1]);
            }
        }

        // causal mask (only near diagonal)
        if (kv0 + 31 > row0) {
#pragma unroll
            for (int nt = 0; nt < 4; nt++) {
                int j0 = kv0 + nt * 8 + t2;
                if (j0 > row0)     S[nt][0] = -INFINITY;
                if (j0 + 1 > row0) S[nt][1] = -INFINITY;
                if (j0 > row1)     S[nt][2] = -INFINITY;
                if (j0 + 1 > row1) S[nt][3] = -INFINITY;
            }
        }

        // online softmax
        float t0m = -INFINITY, t1m = -INFINITY;
#pragma unroll
        for (int nt = 0; nt < 4; nt++) {
            t0m = fmaxf(t0m, fmaxf(S[nt][0], S[nt][1]));
            t1m = fmaxf(t1m, fmaxf(S[nt][2], S[nt][3]));
        }
        t0m = fmaxf(t0m, __shfl_xor_sync(0xffffffffu, t0m, 1));
        t0m = fmaxf(t0m, __shfl_xor_sync(0xffffffffu, t0m, 2));
        t1m = fmaxf(t1m, __shfl_xor_sync(0xffffffffu, t1m, 1));
        t1m = fmaxf(t1m, __shfl_xor_sync(0xffffffffu, t1m, 2));

        float mn0 = fmaxf(m0, t0m);
        float mn1 = fmaxf(m1, t1m);
        float c0 = __expf(m0 - mn0);
        float c1 = __expf(m1 - mn1);
        m0 = mn0; m1 = mn1;

        float ps0 = 0.f, ps1 = 0.f;
#pragma unroll
        for (int nt = 0; nt < 4; nt++) {
            S[nt][0] = __expf(S[nt][0] - mn0);
            S[nt][1] = __expf(S[nt][1] - mn0);
            S[nt][2] = __expf(S[nt][2] - mn1);
            S[nt][3] = __expf(S[nt][3] - mn1);
            ps0 += S[nt][0] + S[nt][1];
            ps1 += S[nt][2] + S[nt][3];
        }
        ps0 += __shfl_xor_sync(0xffffffffu, ps0, 1);
        ps0 += __shfl_xor_sync(0xffffffffu, ps0, 2);
        ps1 += __shfl_xor_sync(0xffffffffu, ps1, 1);
        ps1 += __shfl_xor_sync(0xffffffffu, ps1, 2);
        l0 = l0 * c0 + ps0;
        l1 = l1 * c1 + ps1;

#pragma unroll
        for (int n = 0; n < 8; n++) {
            O[n][0] *= c0; O[n][1] *= c0;
            O[n][2] *= c1; O[n][3] *= c1;
        }

        // P V (split P in-register)
#pragma unroll
        for (int kt2 = 0; kt2 < 2; kt2++) {
            u32 ahf[4], alf[4];
#pragma unroll
            for (int half = 0; half < 2; half++) {
                float* sA = S[kt2 * 2 + half];
                u32 h01 = cvt2bf(sA[0], sA[1]);
                u32 h23 = cvt2bf(sA[2], sA[3]);
                float f0 = __uint_as_float(h01 << 16);
                float f1 = __uint_as_float(h01 & 0xffff0000u);
                float f2 = __uint_as_float(h23 << 16);
                float f3 = __uint_as_float(h23 & 0xffff0000u);
                ahf[half * 2 + 0] = h01;
                ahf[half * 2 + 1] = h23;
                alf[half * 2 + 0] = cvt2bf(sA[0] - f0, sA[1] - f1);
                alf[half * 2 + 1] = cvt2bf(sA[2] - f2, sA[3] - f3);
            }
            const int kc = kt2 * 16;
#pragma unroll
            for (int p = 0; p < 4; p++) {   // nd pairs
                u32 vh[4], vl[4];
                u32 off = (u32)(((p * 16 + brow) * VSTR + kc + bc8) * 2);
                ldsm4(vh, aVh + off);
                ldsm4(vl, aVl + off);
                mma_bf16(O[p * 2 + 0], ahf, vh[0], vh[1]);
                mma_bf16(O[p * 2 + 0], alf, vh[0], vh[1]);
                mma_bf16(O[p * 2 + 0], ahf, vl[0], vl[1]);
                mma_bf16(O[p * 2 + 1], ahf, vh[2], vh[3]);
                mma_bf16(O[p * 2 + 1], alf, vh[2], vh[3]);
                mma_bf16(O[p * 2 + 1], ahf, vl[2], vl[3]);
            }
        }
        __syncthreads();
    }

    // epilogue
    float il0 = 1.f / l0;
    float il1 = 1.f / l1;
    float* y0 = g_y + ((size_t)b * T_ + row0) * DIM_ + h * HD_;
    float* y1 = g_y + ((size_t)b * T_ + row1) * DIM_ + h * HD_;
#pragma unroll
    for (int nd = 0; nd < 8; nd++) {
        int col = nd * 8 + t2;
        *(float2*)(y0 + col) = make_float2(O[nd][0] * il0, O[nd][1] * il0);
        *(float2*)(y1 + col) = make_float2(O[nd][2] * il1, O[nd][3] * il1);
    }
}

// ---------------- launch ---------------------------------------------------
extern "C" void kernel_launch(void* const* d_in, const int* in_sizes, int n_in,
                              void* d_out, int out_size)
{
    const float* x  = (const float*)d_in[0];
    const float* Wq = (const float*)d_in[1];
    const float* Wk = (const float*)d_in[2];
    const float* Wv = (const float*)d_in[3];
    const float* Wp = (const float*)d_in[4];
    float* out = (float*)d_out;

    float* qkv;  cudaGetSymbolAddress((void**)&qkv, g_qkv);
    float* ybuf; cudaGetSymbolAddress((void**)&ybuf, g_y);
    __nv_bfloat16 *xh, *xl, *yh, *yl, *wh, *wl;
    cudaGetSymbolAddress((void**)&xh, g_xh);
    cudaGetSymbolAddress((void**)&xl, g_xl);
    cudaGetSymbolAddress((void**)&yh, g_yh);
    cudaGetSymbolAddress((void**)&yl, g_yl);
    cudaGetSymbolAddress((void**)&wh, g_wh);
    cudaGetSymbolAddress((void**)&wl, g_wl);

    const int M = B_ * T_;  // 16384

    // split inputs/weights into bf16 hi/lo
    split_kernel<<<(M * DIM_) / 256, 256>>>(x, xh, xl);
    split_kernel<<<(512 * 512) / 256, 256>>>(Wq, wh, wl);
    split_kernel<<<(256 * 512) / 256, 256>>>(Wk, wh + (size_t)512 * 512,
                                             wl + (size_t)512 * 512);
    split_kernel<<<(256 * 512) / 256, 256>>>(Wv, wh + (size_t)768 * 512,
                                             wl + (size_t)768 * 512);
    split_kernel<<<(512 * 512) / 256, 256>>>(Wp, wh + (size_t)1024 * 512,
                                             wl + (size_t)1024 * 512);

    // fused QKV projection
    gemm_bf16_kernel<<<dim3(M / 128, 8), 256>>>(xh, xl, 0, qkv, 1024, 0);

    // RMSNorm + RoPE -> split bf16 Q/K; V transpose+split
    rope_kernel<<<M, 256>>>();
    vtrans_kernel<<<dim3(T_ / 64, NKV_, B_), 256>>>();

    // tensor-core flash attention
    attn_kernel<<<dim3(T_ / 64, NH_, B_), 128>>>();

    // output projection
    split_kernel<<<(M * DIM_) / 256, 256>>>(ybuf, yh, yl);
    gemm_bf16_kernel<<<dim3(M / 128, 4), 256>>>(yh, yl, 1024, out, 512, 0);
}